// round 1
// baseline (speedup 1.0000x reference)
#include <cuda_runtime.h>

#define Bb 2
#define Ss 2048
#define Dd 512
#define Hh 8
#define DHh 64
#define CAP 320

// Scratch (device globals: no runtime allocation allowed)
__device__ float g_Q[Bb * Hh * Ss * DHh];            // [B,H,S,dh]  8 MB
__device__ float g_K[Bb * Hh * Ss * DHh];            // [B,H,S,dh]  8 MB
__device__ float g_V[Bb * Ss * DHh];                 // [B,S,dh]    1 MB
__device__ float g_logits[Bb * Hh * Ss * Ss];        // [B,H,S,S] 256 MB
__device__ float g_heads[Bb * Ss * Dd];              // [B,S,D]     8 MB

// ---------------------------------------------------------------------------
// Generic fp32 GEMM: C[z] = A[z] (MxK) * B[z] (KxN or NxK if transB) + bias
// Tile: 128x64, BK=16, 256 threads, 8x4 per thread. All M multiples of 128,
// all N multiples of 64, all K multiples of 16 (true for every call here),
// so no bounds guards are needed.
// headMajorC: scatter C columns as [B,H,S,dh] (n-block == head block, BN=64==dh).
// ---------------------------------------------------------------------------
__global__ __launch_bounds__(256) void sgemm_128x64(
    const float* __restrict__ A, int lda, long sA,
    const float* __restrict__ Bmat, int ldb, long sB, int transB,
    const float* __restrict__ bias,
    float* __restrict__ C, int ldc, long sC, int headMajorC,
    int Kdim)
{
    const int BM = 128, BN = 64, BK = 16;
    __shared__ float As[BK][BM + 4];   // As[k][m]
    __shared__ float Bs[BK][BN + 4];   // Bs[k][n]

    const float* Ab = A + (long)blockIdx.z * sA;
    const float* Bp = Bmat + (long)blockIdx.z * sB;
    float* Cb = C + (long)blockIdx.z * sC;

    int tid = threadIdx.x;
    int tx = tid & 15;     // col group: 4 cols
    int ty = tid >> 4;     // row group: 8 rows
    int m0 = blockIdx.x * BM;
    int n0 = blockIdx.y * BN;

    // staging index precompute
    int ar = tid >> 1;             // 0..127 (A row)
    int ac = (tid & 1) * 8;        // 0 or 8 (A k-col base)
    int br_n = tid >> 2;           // transB: 0..63 (B row = n)
    int bc_k = (tid & 3) * 4;      //        k base
    int br_k = tid >> 4;           // !transB: 0..15 (B row = k)
    int bc_n = (tid & 15) * 4;     //          n base

    float acc[8][4];
#pragma unroll
    for (int i = 0; i < 8; ++i)
#pragma unroll
        for (int j = 0; j < 4; ++j) acc[i][j] = 0.0f;

    for (int k0 = 0; k0 < Kdim; k0 += BK) {
        // --- stage A (transposed into As[k][m]) ---
        {
            const float* ap = Ab + (long)(m0 + ar) * lda + k0 + ac;
            float4 v0 = *(const float4*)(ap);
            float4 v1 = *(const float4*)(ap + 4);
            As[ac + 0][ar] = v0.x; As[ac + 1][ar] = v0.y;
            As[ac + 2][ar] = v0.z; As[ac + 3][ar] = v0.w;
            As[ac + 4][ar] = v1.x; As[ac + 5][ar] = v1.y;
            As[ac + 6][ar] = v1.z; As[ac + 7][ar] = v1.w;
        }
        // --- stage B ---
        if (transB) {
            float4 v = *(const float4*)(Bp + (long)(n0 + br_n) * ldb + k0 + bc_k);
            Bs[bc_k + 0][br_n] = v.x; Bs[bc_k + 1][br_n] = v.y;
            Bs[bc_k + 2][br_n] = v.z; Bs[bc_k + 3][br_n] = v.w;
        } else {
            float4 v = *(const float4*)(Bp + (long)(k0 + br_k) * ldb + n0 + bc_n);
            *(float4*)&Bs[br_k][bc_n] = v;
        }
        __syncthreads();

#pragma unroll
        for (int k = 0; k < BK; ++k) {
            float a[8], b[4];
            *(float4*)&a[0] = *(const float4*)&As[k][ty * 8];
            *(float4*)&a[4] = *(const float4*)&As[k][ty * 8 + 4];
            *(float4*)&b[0] = *(const float4*)&Bs[k][tx * 4];
#pragma unroll
            for (int i = 0; i < 8; ++i)
#pragma unroll
                for (int j = 0; j < 4; ++j)
                    acc[i][j] += a[i] * b[j];
        }
        __syncthreads();
    }

    // --- epilogue ---
    float4 bv = make_float4(0.f, 0.f, 0.f, 0.f);
    if (bias) bv = *(const float4*)(bias + n0 + tx * 4);

#pragma unroll
    for (int i = 0; i < 8; ++i) {
        int m = m0 + ty * 8 + i;
        float4 o;
        o.x = acc[i][0] + bv.x;
        o.y = acc[i][1] + bv.y;
        o.z = acc[i][2] + bv.z;
        o.w = acc[i][3] + bv.w;
        long addr;
        if (headMajorC) {
            int bb = m >> 11;          // m / S
            int ss = m & 2047;         // m % S
            int hh = n0 >> 6;          // head = n-block (BN == dh == 64)
            addr = ((((long)bb * Hh + hh) * Ss) + ss) * DHh + tx * 4;
        } else {
            addr = (long)m * ldc + n0 + tx * 4;
        }
        *(float4*)(Cb + addr) = o;
    }
}

// ---------------------------------------------------------------------------
// Sparsemax + heads + avg_attention.
// Grid: B*S blocks of 256 threads. Warp w handles head w of row (b,i).
// Each lane holds 64 logits in registers. Exact tau via:
//   zmax (warp reduce) -> candidates {z > zmax-1} (superset of support,
//   since g(zmax-1) >= 1 => tau* >= zmax-1) -> ballot-compaction to shared
//   -> Michelot fixed-point (exact). Dense binary-search fallback on overflow.
// ---------------------------------------------------------------------------
__global__ __launch_bounds__(256) void sparsemax_attn(
    const float* __restrict__ logits,   // [B,H,S,S]
    const float* __restrict__ V,        // [B,S,dh]
    float* __restrict__ heads,          // [B,S,D]
    float* __restrict__ avg_out)        // [B,S,S]
{
    __shared__ float s_z[Hh][CAP];
    __shared__ int   s_j[Hh][CAP];
    __shared__ float s_tau[Hh];

    int row = blockIdx.x;
    int b = row >> 11;
    int i = row & 2047;
    int tid = threadIdx.x;
    int w = tid >> 5;
    int lane = tid & 31;

    const float* Lrow = logits + ((((long)b * Hh + w) * Ss) + i) * (long)Ss;

    float z[64];
#pragma unroll
    for (int mm = 0; mm < 16; ++mm) {
        float4 v = *(const float4*)(Lrow + mm * 128 + lane * 4);
        z[mm * 4 + 0] = v.x; z[mm * 4 + 1] = v.y;
        z[mm * 4 + 2] = v.z; z[mm * 4 + 3] = v.w;
    }

    // row max
    float zmax = z[0];
#pragma unroll
    for (int e = 1; e < 64; ++e) zmax = fmaxf(zmax, z[e]);
#pragma unroll
    for (int off = 16; off; off >>= 1)
        zmax = fmaxf(zmax, __shfl_xor_sync(0xffffffffu, zmax, off));

    // compact candidates (deterministic order via ballot prefix)
    float t0 = zmax - 1.0f;
    int cnt = 0;
#pragma unroll
    for (int e = 0; e < 64; ++e) {
        bool pred = z[e] > t0;
        unsigned msk = __ballot_sync(0xffffffffu, pred);
        if (pred) {
            int pos = cnt + __popc(msk & ((1u << lane) - 1u));
            if (pos < CAP) {
                s_z[w][pos] = z[e];
                s_j[w][pos] = (e >> 2) * 128 + lane * 4 + (e & 3);
            }
        }
        cnt += __popc(msk);
    }
    __syncwarp();

    // tau
    float tau = t0;
    if (cnt <= CAP) {
        for (int it = 0; it < 64; ++it) {
            float s = 0.0f; int c = 0;
            for (int e = lane; e < cnt; e += 32) {
                float zz = s_z[w][e];
                if (zz > tau) { s += zz; c++; }
            }
#pragma unroll
            for (int off = 16; off; off >>= 1) {
                s += __shfl_xor_sync(0xffffffffu, s, off);
                c += __shfl_xor_sync(0xffffffffu, c, off);
            }
            float nt = (s - 1.0f) / (float)c;
            if (nt == tau) break;
            tau = nt;
        }
    } else {
        // fallback: dense binary search over register-resident row
        float lo = t0, hi = zmax;
        for (int it = 0; it < 46; ++it) {
            float mid = 0.5f * (lo + hi);
            float s = 0.0f;
#pragma unroll
            for (int e = 0; e < 64; ++e) s += fmaxf(z[e] - mid, 0.0f);
#pragma unroll
            for (int off = 16; off; off >>= 1)
                s += __shfl_xor_sync(0xffffffffu, s, off);
            if (s > 1.0f) lo = mid; else hi = mid;
        }
        tau = 0.5f * (lo + hi);
    }
    if (lane == 0) s_tau[w] = tau;

    // head output: o_d = sum_j p_j * V[b,j,d], only support entries contribute
    const float* Vb = V + (long)b * Ss * DHh;
    float o0 = 0.0f, o1 = 0.0f;
    if (cnt <= CAP) {
        for (int e = 0; e < cnt; ++e) {
            float p = s_z[w][e] - tau;
            if (p > 0.0f) {
                int j = s_j[w][e];
                o0 += p * Vb[(long)j * DHh + lane];
                o1 += p * Vb[(long)j * DHh + lane + 32];
            }
        }
    } else {
        // fallback: dense, broadcast probs across lanes
#pragma unroll 1
        for (int e = 0; e < 64; ++e) {
            float myz = z[e];
            for (int src = 0; src < 32; ++src) {
                float zb = __shfl_sync(0xffffffffu, myz, src);
                float p = zb - tau;
                if (p > 0.0f) {
                    int j = (e >> 2) * 128 + src * 4 + (e & 3);
                    o0 += p * Vb[(long)j * DHh + lane];
                    o1 += p * Vb[(long)j * DHh + lane + 32];
                }
            }
        }
    }
    long hbase = (long)row * Dd + w * DHh;
    heads[hbase + lane] = o0;
    heads[hbase + lane + 32] = o1;

    __syncthreads();

    // avg_attention row: recompute probs from tau (deterministic, L1-hot rows)
    long abase = ((long)b * Ss + i) * (long)Ss;
    for (int j = tid; j < Ss; j += 256) {
        float a = 0.0f;
#pragma unroll
        for (int h = 0; h < Hh; ++h) {
            float zv = logits[((((long)b * Hh + h) * Ss) + i) * (long)Ss + j];
            a += fmaxf(zv - s_tau[h], 0.0f);
        }
        avg_out[abase + j] = 0.125f * a;
    }
}

// ---------------------------------------------------------------------------
extern "C" void kernel_launch(void* const* d_in, const int* in_sizes, int n_in,
                              void* d_out, int out_size)
{
    const float* x    = (const float*)d_in[0];
    const float* Wq   = (const float*)d_in[1];
    const float* bq   = (const float*)d_in[2];
    const float* Wk   = (const float*)d_in[3];
    const float* bk   = (const float*)d_in[4];
    const float* Wv   = (const float*)d_in[5];
    const float* bv   = (const float*)d_in[6];
    const float* Wout = (const float*)d_in[7];
    const float* bout = (const float*)d_in[8];

    float* out   = (float*)d_out;
    float* x_out = out;                              // [B,S,D]
    float* avg   = out + (long)Bb * Ss * Dd;         // [B,S,S]

    float *Qp, *Kp, *Vp, *Lp, *Hp;
    cudaGetSymbolAddress((void**)&Qp, g_Q);
    cudaGetSymbolAddress((void**)&Kp, g_K);
    cudaGetSymbolAddress((void**)&Vp, g_V);
    cudaGetSymbolAddress((void**)&Lp, g_logits);
    cudaGetSymbolAddress((void**)&Hp, g_heads);

    const int M = Bb * Ss;   // 4096

    // Q = x@Wq + bq  -> [B,H,S,dh]
    sgemm_128x64<<<dim3(M / 128, Dd / 64, 1), 256>>>(
        x, Dd, 0, Wq, Dd, 0, 0, bq, Qp, 0, 0, 1, Dd);
    // K = x@Wk + bk  -> [B,H,S,dh]
    sgemm_128x64<<<dim3(M / 128, Dd / 64, 1), 256>>>(
        x, Dd, 0, Wk, Dd, 0, 0, bk, Kp, 0, 0, 1, Dd);
    // V = x@Wv + bv  -> [B,S,dh]
    sgemm_128x64<<<dim3(M / 128, DHh / 64, 1), 256>>>(
        x, Dd, 0, Wv, DHh, 0, 0, bv, Vp, DHh, 0, 0, Dd);

    // logits[z] = Q_z @ K_z^T, z = b*H + h (batched over 16 heads)
    sgemm_128x64<<<dim3(Ss / 128, Ss / 64, Bb * Hh), 256>>>(
        Qp, DHh, (long)Ss * DHh,
        Kp, DHh, (long)Ss * DHh, 1,
        nullptr,
        Lp, Ss, (long)Ss * Ss, 0, DHh);

    // sparsemax + heads + avg_attention
    sparsemax_attn<<<Bb * Ss, 256>>>(Lp, Vp, Hp, avg);

    // x_out = heads @ Wout + bout
    sgemm_128x64<<<dim3(M / 128, Dd / 64, 1), 256>>>(
        Hp, Dd, 0, Wout, Dd, 0, 0, bout, x_out, Dd, 0, 0, Dd);
}

// round 2
// speedup vs baseline: 1.2249x; 1.2249x over previous
#include <cuda_runtime.h>

#define Bb 2
#define Ss 2048
#define Dd 512
#define Hh 8
#define DHh 64
#define CAP 320

// Scratch (device globals: no runtime allocation allowed)
__device__ float g_Q[Bb * Hh * Ss * DHh];            // [B,H,S,dh]  8 MB
__device__ float g_K[Bb * Hh * Ss * DHh];            // [B,H,S,dh]  8 MB
__device__ float g_V[Bb * Ss * DHh];                 // [B,S,dh]    1 MB
__device__ float g_logits[Bb * Hh * Ss * Ss];        // [B,H,S,S] 256 MB
__device__ float g_heads[Bb * Ss * Dd];              // [B,S,D]     8 MB

// ---------------------------------------------------------------------------
// fp32 SGEMM (projections): C[z] = A (MxK) * B (KxN or NxK if transB) + bias
// ---------------------------------------------------------------------------
__global__ __launch_bounds__(256) void sgemm_128x64(
    const float* __restrict__ A, int lda, long sA,
    const float* __restrict__ Bmat, int ldb, long sB, int transB,
    const float* __restrict__ bias,
    float* __restrict__ C, int ldc, long sC, int headMajorC,
    int Kdim)
{
    const int BM = 128, BN = 64, BK = 16;
    __shared__ float As[BK][BM + 4];
    __shared__ float Bs[BK][BN + 4];

    const float* Ab = A + (long)blockIdx.z * sA;
    const float* Bp = Bmat + (long)blockIdx.z * sB;
    float* Cb = C + (long)blockIdx.z * sC;

    int tid = threadIdx.x;
    int tx = tid & 15;
    int ty = tid >> 4;
    int m0 = blockIdx.x * BM;
    int n0 = blockIdx.y * BN;

    int ar = tid >> 1;
    int ac = (tid & 1) * 8;
    int br_n = tid >> 2;
    int bc_k = (tid & 3) * 4;
    int br_k = tid >> 4;
    int bc_n = (tid & 15) * 4;

    float acc[8][4];
#pragma unroll
    for (int i = 0; i < 8; ++i)
#pragma unroll
        for (int j = 0; j < 4; ++j) acc[i][j] = 0.0f;

    for (int k0 = 0; k0 < Kdim; k0 += BK) {
        {
            const float* ap = Ab + (long)(m0 + ar) * lda + k0 + ac;
            float4 v0 = *(const float4*)(ap);
            float4 v1 = *(const float4*)(ap + 4);
            As[ac + 0][ar] = v0.x; As[ac + 1][ar] = v0.y;
            As[ac + 2][ar] = v0.z; As[ac + 3][ar] = v0.w;
            As[ac + 4][ar] = v1.x; As[ac + 5][ar] = v1.y;
            As[ac + 6][ar] = v1.z; As[ac + 7][ar] = v1.w;
        }
        if (transB) {
            float4 v = *(const float4*)(Bp + (long)(n0 + br_n) * ldb + k0 + bc_k);
            Bs[bc_k + 0][br_n] = v.x; Bs[bc_k + 1][br_n] = v.y;
            Bs[bc_k + 2][br_n] = v.z; Bs[bc_k + 3][br_n] = v.w;
        } else {
            float4 v = *(const float4*)(Bp + (long)(k0 + br_k) * ldb + n0 + bc_n);
            *(float4*)&Bs[br_k][bc_n] = v;
        }
        __syncthreads();

#pragma unroll
        for (int k = 0; k < BK; ++k) {
            float a[8], b[4];
            *(float4*)&a[0] = *(const float4*)&As[k][ty * 8];
            *(float4*)&a[4] = *(const float4*)&As[k][ty * 8 + 4];
            *(float4*)&b[0] = *(const float4*)&Bs[k][tx * 4];
#pragma unroll
            for (int i = 0; i < 8; ++i)
#pragma unroll
                for (int j = 0; j < 4; ++j)
                    acc[i][j] += a[i] * b[j];
        }
        __syncthreads();
    }

    float4 bv = make_float4(0.f, 0.f, 0.f, 0.f);
    if (bias) bv = *(const float4*)(bias + n0 + tx * 4);

#pragma unroll
    for (int i = 0; i < 8; ++i) {
        int m = m0 + ty * 8 + i;
        float4 o;
        o.x = acc[i][0] + bv.x;
        o.y = acc[i][1] + bv.y;
        o.z = acc[i][2] + bv.z;
        o.w = acc[i][3] + bv.w;
        long addr;
        if (headMajorC) {
            int bb = m >> 11;
            int ss = m & 2047;
            int hh = n0 >> 6;
            addr = ((((long)bb * Hh + hh) * Ss) + ss) * DHh + tx * 4;
        } else {
            addr = (long)m * ldc + n0 + tx * 4;
        }
        *(float4*)(Cb + addr) = o;
    }
}

// ---------------------------------------------------------------------------
// Logits: L[z] (2048x2048) = Q[z](2048x64) @ K[z](2048x64)^T, tf32 tensor cores.
// grid: (n_tiles=16, m_tiles=16, z=16). 256 threads, 8 warps in 4(m) x 2(n),
// warp tile 32x64 = 2x8 mma tiles of m16n8k8. K=64 staged once (8 k-steps).
// Shared stride 68 floats: verified conflict-free for both fragment patterns.
// ---------------------------------------------------------------------------
__device__ __forceinline__ unsigned f2tf32(float f) {
    unsigned u;
    asm("cvt.rna.tf32.f32 %0, %1;" : "=r"(u) : "f"(f));
    return u;
}

#define QK_LDS 68
#define QK_SMEM_BYTES (2 * 128 * QK_LDS * 4)

__global__ __launch_bounds__(256) void qk_tf32_kernel(
    const float* __restrict__ Q, const float* __restrict__ K,
    float* __restrict__ L)
{
    extern __shared__ unsigned sm[];
    unsigned* Qs = sm;                       // [128][68]
    unsigned* Ks = sm + 128 * QK_LDS;        // [128][68]  (row = key index n, col = k)

    int tid = threadIdx.x;
    int wid = tid >> 5, lane = tid & 31;
    int wm = wid & 3;        // 0..3  -> 32-row slab
    int wn = wid >> 2;       // 0..1  -> 64-col slab
    int g = lane >> 2;       // group id (0..7)
    int tg = lane & 3;       // thread in group (0..3)

    long zoff = (long)blockIdx.z * Ss * DHh;
    const float* Qg = Q + zoff + (long)(blockIdx.y * 128) * DHh;
    const float* Kg = K + zoff + (long)(blockIdx.x * 128) * DHh;

    // stage both tiles (each thread: 8 rows x one float4)
#pragma unroll
    for (int p = 0; p < 8; ++p) {
        int r = (tid >> 4) + p * 16;
        int c = (tid & 15) * 4;
        float4 v = *(const float4*)(Qg + r * DHh + c);
        unsigned* q = Qs + r * QK_LDS + c;
        q[0] = f2tf32(v.x); q[1] = f2tf32(v.y); q[2] = f2tf32(v.z); q[3] = f2tf32(v.w);
        float4 w = *(const float4*)(Kg + r * DHh + c);
        unsigned* kk = Ks + r * QK_LDS + c;
        kk[0] = f2tf32(w.x); kk[1] = f2tf32(w.y); kk[2] = f2tf32(w.z); kk[3] = f2tf32(w.w);
    }
    __syncthreads();

    float acc[2][8][4];
#pragma unroll
    for (int mt = 0; mt < 2; ++mt)
#pragma unroll
        for (int nt = 0; nt < 8; ++nt)
#pragma unroll
            for (int e = 0; e < 4; ++e) acc[mt][nt][e] = 0.0f;

#pragma unroll
    for (int ks = 0; ks < 8; ++ks) {
        int kc = ks * 8;
        unsigned a[2][4];
#pragma unroll
        for (int mt = 0; mt < 2; ++mt) {
            int r = wm * 32 + mt * 16 + g;
            a[mt][0] = Qs[(r) * QK_LDS + kc + tg];
            a[mt][1] = Qs[(r + 8) * QK_LDS + kc + tg];
            a[mt][2] = Qs[(r) * QK_LDS + kc + tg + 4];
            a[mt][3] = Qs[(r + 8) * QK_LDS + kc + tg + 4];
        }
        unsigned b[8][2];
#pragma unroll
        for (int nt = 0; nt < 8; ++nt) {
            int n = wn * 64 + nt * 8 + g;
            b[nt][0] = Ks[n * QK_LDS + kc + tg];
            b[nt][1] = Ks[n * QK_LDS + kc + tg + 4];
        }
#pragma unroll
        for (int mt = 0; mt < 2; ++mt)
#pragma unroll
            for (int nt = 0; nt < 8; ++nt) {
                asm volatile(
                    "mma.sync.aligned.m16n8k8.row.col.f32.tf32.tf32.f32 "
                    "{%0,%1,%2,%3}, {%4,%5,%6,%7}, {%8,%9}, {%0,%1,%2,%3};"
                    : "+f"(acc[mt][nt][0]), "+f"(acc[mt][nt][1]),
                      "+f"(acc[mt][nt][2]), "+f"(acc[mt][nt][3])
                    : "r"(a[mt][0]), "r"(a[mt][1]), "r"(a[mt][2]), "r"(a[mt][3]),
                      "r"(b[nt][0]), "r"(b[nt][1]));
            }
    }

    // epilogue: float2 stores; each quad covers 32 contiguous bytes per row
    float* Lz = L + (long)blockIdx.z * Ss * Ss;
    int rbase = blockIdx.y * 128 + wm * 32 + g;
    int cbase = blockIdx.x * 128 + wn * 64 + tg * 2;
#pragma unroll
    for (int mt = 0; mt < 2; ++mt) {
#pragma unroll
        for (int nt = 0; nt < 8; ++nt) {
            int r = rbase + mt * 16;
            int c = cbase + nt * 8;
            *(float2*)(Lz + (long)r * Ss + c) =
                make_float2(acc[mt][nt][0], acc[mt][nt][1]);
            *(float2*)(Lz + (long)(r + 8) * Ss + c) =
                make_float2(acc[mt][nt][2], acc[mt][nt][3]);
        }
    }
}

// ---------------------------------------------------------------------------
// Sparsemax + heads + avg_attention (single logits read; avg built from the
// candidate lists in shared — no second 256MB pass).
// ---------------------------------------------------------------------------
__global__ __launch_bounds__(256) void sparsemax_attn(
    const float* __restrict__ logits,   // [B,H,S,S]
    const float* __restrict__ V,        // [B,S,dh]
    float* __restrict__ heads,          // [B,S,D]
    float* __restrict__ avg_out)        // [B,S,S]
{
    __shared__ float s_z[Hh][CAP];
    __shared__ int   s_j[Hh][CAP];
    __shared__ float s_tau[Hh];
    __shared__ int   s_cnt[Hh];
    __shared__ float s_avg[Ss];

    int row = blockIdx.x;
    int b = row >> 11;
    int i = row & 2047;
    int tid = threadIdx.x;
    int w = tid >> 5;
    int lane = tid & 31;

    // zero the shared avg row early (independent of warp work)
    for (int j = tid; j < Ss; j += 256) s_avg[j] = 0.0f;

    const float* Lrow = logits + ((((long)b * Hh + w) * Ss) + i) * (long)Ss;

    float z[64];
#pragma unroll
    for (int mm = 0; mm < 16; ++mm) {
        float4 v = *(const float4*)(Lrow + mm * 128 + lane * 4);
        z[mm * 4 + 0] = v.x; z[mm * 4 + 1] = v.y;
        z[mm * 4 + 2] = v.z; z[mm * 4 + 3] = v.w;
    }

    // row max
    float zmax = z[0];
#pragma unroll
    for (int e = 1; e < 64; ++e) zmax = fmaxf(zmax, z[e]);
#pragma unroll
    for (int off = 16; off; off >>= 1)
        zmax = fmaxf(zmax, __shfl_xor_sync(0xffffffffu, zmax, off));

    // compact candidates {z > zmax-1} (superset of support since tau >= zmax-1)
    float t0 = zmax - 1.0f;
    int cnt = 0;
#pragma unroll
    for (int e = 0; e < 64; ++e) {
        bool pred = z[e] > t0;
        unsigned msk = __ballot_sync(0xffffffffu, pred);
        if (pred) {
            int pos = cnt + __popc(msk & ((1u << lane) - 1u));
            if (pos < CAP) {
                s_z[w][pos] = z[e];
                s_j[w][pos] = (e >> 2) * 128 + lane * 4 + (e & 3);
            }
        }
        cnt += __popc(msk);
    }
    __syncwarp();

    // exact tau (Michelot on candidates; dense bisection fallback)
    float tau = t0;
    if (cnt <= CAP) {
        for (int it = 0; it < 64; ++it) {
            float s = 0.0f; int c = 0;
            for (int e = lane; e < cnt; e += 32) {
                float zz = s_z[w][e];
                if (zz > tau) { s += zz; c++; }
            }
#pragma unroll
            for (int off = 16; off; off >>= 1) {
                s += __shfl_xor_sync(0xffffffffu, s, off);
                c += __shfl_xor_sync(0xffffffffu, c, off);
            }
            float nt = (s - 1.0f) / (float)c;
            if (nt == tau) break;
            tau = nt;
        }
    } else {
        float lo = t0, hi = zmax;
        for (int it = 0; it < 46; ++it) {
            float mid = 0.5f * (lo + hi);
            float s = 0.0f;
#pragma unroll
            for (int e = 0; e < 64; ++e) s += fmaxf(z[e] - mid, 0.0f);
#pragma unroll
            for (int off = 16; off; off >>= 1)
                s += __shfl_xor_sync(0xffffffffu, s, off);
            if (s > 1.0f) lo = mid; else hi = mid;
        }
        tau = 0.5f * (lo + hi);
    }
    if (lane == 0) { s_tau[w] = tau; s_cnt[w] = cnt; }

    // head output (sparse over candidates)
    const float* Vb = V + (long)b * Ss * DHh;
    float o0 = 0.0f, o1 = 0.0f;
    if (cnt <= CAP) {
        for (int e = 0; e < cnt; ++e) {
            float p = s_z[w][e] - tau;
            if (p > 0.0f) {
                int j = s_j[w][e];
                o0 += p * Vb[(long)j * DHh + lane];
                o1 += p * Vb[(long)j * DHh + lane + 32];
            }
        }
    } else {
#pragma unroll 1
        for (int e = 0; e < 64; ++e) {
            float myz = z[e];
            for (int src = 0; src < 32; ++src) {
                float zb = __shfl_sync(0xffffffffu, myz, src);
                float p = zb - tau;
                if (p > 0.0f) {
                    int j = (e >> 2) * 128 + src * 4 + (e & 3);
                    o0 += p * Vb[(long)j * DHh + lane];
                    o1 += p * Vb[(long)j * DHh + lane + 32];
                }
            }
        }
    }
    long hbase = (long)row * Dd + w * DHh;
    heads[hbase + lane] = o0;
    heads[hbase + lane + 32] = o1;

    __syncthreads();

    // overflowed heads (never expected): dense scatter into s_avg
    if (s_cnt[w] > CAP) {
#pragma unroll
        for (int e = 0; e < 64; ++e) {
            float p = z[e] - tau;
            if (p > 0.0f) {
                int j = (e >> 2) * 128 + lane * 4 + (e & 3);
                atomicAdd(&s_avg[j], p);
            }
        }
    }
    __syncthreads();

    // deterministic ownership scan: thread t owns columns j with (j & 255)==t
    float rv[8];
#pragma unroll
    for (int k = 0; k < 8; ++k) rv[k] = s_avg[tid + k * 256];
#pragma unroll
    for (int h = 0; h < Hh; ++h) {
        int c = s_cnt[h];
        if (c <= CAP) {
            float th = s_tau[h];
            for (int e = 0; e < c; ++e) {          // broadcast reads
                int j = s_j[h][e];
                if ((j & 255) == tid) {
                    float p = s_z[h][e] - th;
                    if (p > 0.0f) rv[j >> 8] += p;
                }
            }
        }
    }
    long abase = ((long)b * Ss + i) * (long)Ss;
#pragma unroll
    for (int k = 0; k < 8; ++k)
        avg_out[abase + tid + k * 256] = 0.125f * rv[k];
}

// ---------------------------------------------------------------------------
extern "C" void kernel_launch(void* const* d_in, const int* in_sizes, int n_in,
                              void* d_out, int out_size)
{
    const float* x    = (const float*)d_in[0];
    const float* Wq   = (const float*)d_in[1];
    const float* bq   = (const float*)d_in[2];
    const float* Wk   = (const float*)d_in[3];
    const float* bk   = (const float*)d_in[4];
    const float* Wv   = (const float*)d_in[5];
    const float* bv   = (const float*)d_in[6];
    const float* Wout = (const float*)d_in[7];
    const float* bout = (const float*)d_in[8];

    float* out   = (float*)d_out;
    float* x_out = out;                              // [B,S,D]
    float* avg   = out + (long)Bb * Ss * Dd;         // [B,S,S]

    float *Qp, *Kp, *Vp, *Lp, *Hp;
    cudaGetSymbolAddress((void**)&Qp, g_Q);
    cudaGetSymbolAddress((void**)&Kp, g_K);
    cudaGetSymbolAddress((void**)&Vp, g_V);
    cudaGetSymbolAddress((void**)&Lp, g_logits);
    cudaGetSymbolAddress((void**)&Hp, g_heads);

    cudaFuncSetAttribute(qk_tf32_kernel,
                         cudaFuncAttributeMaxDynamicSharedMemorySize,
                         QK_SMEM_BYTES);

    const int M = Bb * Ss;   // 4096

    // Q = x@Wq + bq  -> [B,H,S,dh]
    sgemm_128x64<<<dim3(M / 128, Dd / 64, 1), 256>>>(
        x, Dd, 0, Wq, Dd, 0, 0, bq, Qp, 0, 0, 1, Dd);
    // K = x@Wk + bk  -> [B,H,S,dh]
    sgemm_128x64<<<dim3(M / 128, Dd / 64, 1), 256>>>(
        x, Dd, 0, Wk, Dd, 0, 0, bk, Kp, 0, 0, 1, Dd);
    // V = x@Wv + bv  -> [B,S,dh]
    sgemm_128x64<<<dim3(M / 128, DHh / 64, 1), 256>>>(
        x, Dd, 0, Wv, DHh, 0, 0, bv, Vp, DHh, 0, 0, Dd);

    // logits via tf32 tensor cores (batched over 16 (b,h) slices)
    qk_tf32_kernel<<<dim3(Ss / 128, Ss / 128, Bb * Hh), 256, QK_SMEM_BYTES>>>(
        Qp, Kp, Lp);

    // sparsemax + heads + avg_attention
    sparsemax_attn<<<Bb * Ss, 256>>>(Lp, Vp, Hp, avg);

    // x_out = heads @ Wout + bout
    sgemm_128x64<<<dim3(M / 128, Dd / 64, 1), 256>>>(
        Hp, Dd, 0, Wout, Dd, 0, 0, bout, x_out, Dd, 0, 0, Dd);
}